// round 3
// baseline (speedup 1.0000x reference)
#include <cuda_runtime.h>
#include <cuda_fp16.h>
#include <cstdint>

// ===================== problem constants =====================
#define DIMD 1024
#define BATCH 65536
#define NITERS 20
#define NCTA_SINK 128
#define ROWS_PER_CTA 8     // 128 CTAs * 8 rows = 1024

// ===================== device globals (scratch; static, never allocated) =====================
__device__ __half  g_P[DIMD * DIMD];            // Sinkhorn P (row-major = K-major B operand)
__device__ __half  g_A16[(size_t)BATCH * DIMD]; // fp16 copy of embeddings (prepass output)
__device__ float2  g_part[NCTA_SINK * DIMD];    // per-CTA column partials (max, sumexp)
__device__ float   g_colLSE[DIMD];
__device__ unsigned g_bar;                      // monotonic grid barrier counter
__device__ unsigned g_done;                     // end-of-kernel reset rendezvous

// ===================== small PTX helpers (plain sm_103-legal only) =====================
__device__ __forceinline__ uint32_t smem_to_u32(const void* p) {
    uint32_t a;
    asm("{ .reg .u64 t; cvta.to.shared.u64 t, %1; cvt.u32.u64 %0, t; }" : "=r"(a) : "l"(p));
    return a;
}

#define CP_ASYNC16(dst, src) \
    asm volatile("cp.async.cg.shared.global [%0], [%1], 16;" :: "r"(dst), "l"(src) : "memory")
#define CP_ASYNC_COMMIT() asm volatile("cp.async.commit_group;" ::: "memory")
#define CP_ASYNC_WAIT1()  asm volatile("cp.async.wait_group 1;" ::: "memory")

__device__ __forceinline__ void ldsm_x4(uint32_t* r, uint32_t addr) {
    asm volatile("ldmatrix.sync.aligned.m8n8.x4.shared.b16 {%0,%1,%2,%3}, [%4];"
                 : "=r"(r[0]), "=r"(r[1]), "=r"(r[2]), "=r"(r[3]) : "r"(addr));
}
__device__ __forceinline__ void mma16816(float* d, const uint32_t* a, uint32_t b0, uint32_t b1) {
    asm volatile("mma.sync.aligned.m16n8k16.row.col.f32.f16.f16.f32 "
                 "{%0,%1,%2,%3}, {%4,%5,%6,%7}, {%8,%9}, {%0,%1,%2,%3};"
                 : "+f"(d[0]), "+f"(d[1]), "+f"(d[2]), "+f"(d[3])
                 : "r"(a[0]), "r"(a[1]), "r"(a[2]), "r"(a[3]), "r"(b0), "r"(b1));
}

// ===================== Sinkhorn: one persistent kernel =====================
__device__ __forceinline__ void grid_barrier(unsigned* p_target) {
    __syncthreads();
    if (threadIdx.x == 0) {
        __threadfence();
        atomicAdd(&g_bar, 1u);
        const unsigned tgt = *p_target;
        while (*((const volatile unsigned*)&g_bar) < tgt) { __nanosleep(64); }
        __threadfence();
    }
    __syncthreads();
    *p_target += gridDim.x;
}

__global__ void __launch_bounds__(256)
sinkhorn_kernel(const float* __restrict__ log_scores) {
    __shared__ float rows[ROWS_PER_CTA][DIMD];   // 32 KB
    const int tid  = threadIdx.x;
    const int warp = tid >> 5;
    const int lane = tid & 31;
    const int cta  = blockIdx.x;
    const int rbase = cta * ROWS_PER_CTA;

    for (int i = tid; i < ROWS_PER_CTA * DIMD; i += 256)
        rows[i >> 10][i & 1023] = log_scores[(size_t)rbase * DIMD + i];
    __syncthreads();

    unsigned bar_target = gridDim.x;

    for (int iter = 0; iter < NITERS; ++iter) {
        // ---- row pass: warp w owns row w; fold in pending column subtraction ----
        {
            float v[32];
            float m = -1e30f;
            #pragma unroll
            for (int j = 0; j < 32; ++j) {
                const int col = lane + j * 32;
                float x = rows[warp][col];
                if (iter > 0) x -= g_colLSE[col];
                v[j] = x;
                m = fmaxf(m, x);
            }
            #pragma unroll
            for (int o = 16; o; o >>= 1) m = fmaxf(m, __shfl_xor_sync(0xFFFFFFFFu, m, o));
            float s = 0.f;
            #pragma unroll
            for (int j = 0; j < 32; ++j) s += expf(v[j] - m);
            #pragma unroll
            for (int o = 16; o; o >>= 1) s += __shfl_xor_sync(0xFFFFFFFFu, s, o);
            const float lse = m + logf(s);
            #pragma unroll
            for (int j = 0; j < 32; ++j) rows[warp][lane + j * 32] = v[j] - lse;
        }
        __syncthreads();

        // ---- column partials over this CTA's 8 rows ----
        #pragma unroll
        for (int c = 0; c < 4; ++c) {
            const int col = tid + c * 256;
            float m2 = -1e30f;
            float vv[ROWS_PER_CTA];
            #pragma unroll
            for (int r = 0; r < ROWS_PER_CTA; ++r) { vv[r] = rows[r][col]; m2 = fmaxf(m2, vv[r]); }
            float s2 = 0.f;
            #pragma unroll
            for (int r = 0; r < ROWS_PER_CTA; ++r) s2 += expf(vv[r] - m2);
            g_part[cta * DIMD + col] = make_float2(m2, s2);
        }
        grid_barrier(&bar_target);

        // ---- column reduce: CTA b owns columns [8b, 8b+8) ----
        {
            const int col = cta * 8 + warp;
            float m = -1e30f, s = 0.f;
            for (int p = lane; p < NCTA_SINK; p += 32) {
                const float2 ps = g_part[p * DIMD + col];
                const float nm = fmaxf(m, ps.x);
                s = s * expf(m - nm) + ps.y * expf(ps.x - nm);
                m = nm;
            }
            #pragma unroll
            for (int o = 16; o; o >>= 1) {
                const float om = __shfl_xor_sync(0xFFFFFFFFu, m, o);
                const float os = __shfl_xor_sync(0xFFFFFFFFu, s, o);
                const float nm = fmaxf(m, om);
                s = s * expf(m - nm) + os * expf(om - nm);
                m = nm;
            }
            if (lane == 0) g_colLSE[col] = m + logf(s);
        }
        grid_barrier(&bar_target);
    }

    // ---- final: apply last column LSE, exponentiate, emit P as fp16 (K-major B) ----
    for (int i = tid; i < ROWS_PER_CTA * DIMD; i += 256) {
        const int r = i >> 10, col = i & 1023;
        const float x = rows[r][col] - g_colLSE[col];
        g_P[(size_t)(rbase + r) * DIMD + col] = __float2half(expf(x));
    }

    // ---- reset barrier counters for the next graph replay ----
    __syncthreads();
    if (threadIdx.x == 0) {
        __threadfence();
        atomicAdd(&g_done, 1u);
        if (blockIdx.x == 0) {
            while (*((const volatile unsigned*)&g_done) < gridDim.x) { __nanosleep(64); }
            g_bar = 0u;
            g_done = 0u;
            __threadfence();
        }
    }
}

// ===================== prepass: embeddings fp32 -> fp16 =====================
__global__ void __launch_bounds__(256)
cvt_kernel(const float4* __restrict__ A) {
    const int n4 = (BATCH / 4) * DIMD;   // 16M float4
    uint2* dst = reinterpret_cast<uint2*>(g_A16);
    for (int i = blockIdx.x * 256 + threadIdx.x; i < n4; i += gridDim.x * 256) {
        const float4 v = A[i];
        __half2 h0 = __floats2half2_rn(v.x, v.y);
        __half2 h1 = __floats2half2_rn(v.z, v.w);
        dst[i] = make_uint2(*reinterpret_cast<uint32_t*>(&h0),
                            *reinterpret_cast<uint32_t*>(&h1));
    }
}

// ===================== GEMM: out = A16 @ P^T  (mma.sync m16n8k16, cp.async 3-stage) =====================
// CTA tile 128x128, warp layout 4(m) x 2(n), warp tile 32x64, K-stage 64 (16 stages).
// smem: 3 stages x (A 16KB + B 16KB) = 96KB.  Swizzle: off ^ ((off>>3)&0x70) == row*128 + (kb ^ ((row&7)<<4)).
#define KSTAGES 16
#define STAGE_BYTES 16384
#define B_BASE (3 * STAGE_BYTES)
#define GSMEM_BYTES (6 * STAGE_BYTES)

__global__ void __launch_bounds__(256, 2)
gemm_kernel(float* __restrict__ out) {
    extern __shared__ __align__(1024) char smem[];
    const uint32_t sb = smem_to_u32(smem);
    const int tid  = threadIdx.x;
    const int wid  = tid >> 5;
    const int lane = tid & 31;

    // ntile fast-moving -> 8 consecutive CTAs share one A row-block (L2 reuse of A)
    const int ntile = blockIdx.x & 7;
    const int mtile = blockIdx.x >> 3;
    const int m0 = mtile * 128;
    const int n0 = ntile * 128;

    const __half* Ag = g_A16 + (size_t)m0 * DIMD;
    const __half* Bg = g_P   + (size_t)n0 * DIMD;

    // ---- cp.async stage issue (A: 4 chunks/thread, B: 4 chunks/thread, 16B each) ----
    // chunk idx over 1024 per tile: row = idx>>3 (128 rows), c = idx&7 (8 x 16B per 128B row)
    const int c_row = tid >> 1;               // 0..127  (2 threads per row, 4 rows-groups... )
    // simpler: idx = tid + i*256
#define ISSUE_STAGE(st, buf)                                                     \
    {                                                                            \
        const __half* asrc = Ag + (st) * 64;                                     \
        const __half* bsrc = Bg + (st) * 64;                                     \
        const uint32_t abase = sb + (buf) * STAGE_BYTES;                         \
        const uint32_t bbase = sb + B_BASE + (buf) * STAGE_BYTES;                \
        _Pragma("unroll")                                                        \
        for (int i = 0; i < 4; ++i) {                                            \
            const int idx = tid + i * 256;                                       \
            const int r = idx >> 3, c = idx & 7;                                 \
            const uint32_t sw = (uint32_t)(r * 128 + ((c * 16) ^ ((r & 7) << 4)));\
            CP_ASYNC16(abase + sw, asrc + (size_t)r * DIMD + c * 8);             \
            CP_ASYNC16(bbase + sw, bsrc + (size_t)r * DIMD + c * 8);             \
        }                                                                        \
        CP_ASYNC_COMMIT();                                                       \
    }

    // ---- per-lane ldmatrix address constants ----
    const int warp_m = wid >> 1;   // 0..3
    const int warp_n = wid & 1;    // 0..1

    // A fragments (non-trans): matrix order a0..a3 = (r0-7,k0-7)(r8-15,k0-7)(r0-7,k8-15)(r8-15,k8-15)
    int a_pre[2], a_sw[2];
    {
        const int rr = ((lane >> 3) & 1) * 8 + (lane & 7);
        #pragma unroll
        for (int mt = 0; mt < 2; ++mt) {
            const int row = warp_m * 32 + mt * 16 + rr;
            a_pre[mt] = row * 128;
            a_sw[mt]  = (row & 7) << 4;
        }
    }
    const int a_k16 = ((lane >> 4) & 1) * 16;   // +8 halves = +16B

    // B fragments (non-trans, TN): for an n16 pair: (n0-7,k0-7)(n0-7,k8-15)(n8-15,k0-7)(n8-15,k8-15)
    int b_pre[4], b_sw[4];
    {
        const int rr = ((lane >> 4) & 1) * 8 + (lane & 7);
        #pragma unroll
        for (int np = 0; np < 4; ++np) {
            const int row = warp_n * 64 + np * 16 + rr;
            b_pre[np] = row * 128;
            b_sw[np]  = (row & 7) << 4;
        }
    }
    const int b_k16 = ((lane >> 3) & 1) * 16;

    float acc[2][8][4];
    #pragma unroll
    for (int mt = 0; mt < 2; ++mt)
        #pragma unroll
        for (int nt = 0; nt < 8; ++nt)
            #pragma unroll
            for (int j = 0; j < 4; ++j) acc[mt][nt][j] = 0.f;

    // prologue: stages 0 and 1 in flight
    ISSUE_STAGE(0, 0);
    ISSUE_STAGE(1, 1);

    for (int s = 0; s < KSTAGES; ++s) {
        const int buf = s % 3;
        CP_ASYNC_WAIT1();
        __syncthreads();
        if (s + 2 < KSTAGES) { ISSUE_STAGE(s + 2, (s + 2) % 3); }
        else                 { CP_ASYNC_COMMIT(); }

        const uint32_t Ab = sb + buf * STAGE_BYTES;
        const uint32_t Bb = sb + B_BASE + buf * STAGE_BYTES;
        #pragma unroll
        for (int ks = 0; ks < 4; ++ks) {
            const int kb = ks * 32;
            uint32_t av[2][4];
            #pragma unroll
            for (int mt = 0; mt < 2; ++mt)
                ldsm_x4(av[mt], Ab + a_pre[mt] + ((kb | a_k16) ^ a_sw[mt]));
            uint32_t bv[4][4];
            #pragma unroll
            for (int np = 0; np < 4; ++np)
                ldsm_x4(bv[np], Bb + b_pre[np] + ((kb | b_k16) ^ b_sw[np]));
            #pragma unroll
            for (int mt = 0; mt < 2; ++mt)
                #pragma unroll
                for (int np = 0; np < 4; ++np) {
                    mma16816(acc[mt][2 * np + 0], av[mt], bv[np][0], bv[np][1]);
                    mma16816(acc[mt][2 * np + 1], av[mt], bv[np][2], bv[np][3]);
                }
        }
    }
#undef ISSUE_STAGE

    // ---- epilogue: direct coalesced STG.64 (4 lanes x 8B = 32B sectors, fully used) ----
    const int r0c = lane >> 2;          // 0..7
    const int c0c = (lane & 3) * 2;     // 0,2,4,6
    #pragma unroll
    for (int mt = 0; mt < 2; ++mt) {
        const int row_base = m0 + warp_m * 32 + mt * 16 + r0c;
        #pragma unroll
        for (int nt = 0; nt < 8; ++nt) {
            const int col = n0 + warp_n * 64 + nt * 8 + c0c;
            float2 v0 = make_float2(acc[mt][nt][0], acc[mt][nt][1]);
            float2 v1 = make_float2(acc[mt][nt][2], acc[mt][nt][3]);
            *reinterpret_cast<float2*>(out + (size_t)row_base * DIMD + col)       = v0;
            *reinterpret_cast<float2*>(out + (size_t)(row_base + 8) * DIMD + col) = v1;
        }
    }
}

// ===================== launch =====================
extern "C" void kernel_launch(void* const* d_in, const int* in_sizes, int n_in,
                              void* d_out, int out_size) {
    const float* emb;
    const float* ls;
    if (n_in >= 2 && in_sizes[0] == DIMD * DIMD && in_sizes[1] != DIMD * DIMD) {
        ls  = (const float*)d_in[0];
        emb = (const float*)d_in[1];
    } else {
        emb = (const float*)d_in[0];
        ls  = (const float*)d_in[1];
    }
    float* out = (float*)d_out;

    static bool attr_done = false;
    if (!attr_done) {
        cudaFuncSetAttribute(gemm_kernel, cudaFuncAttributeMaxDynamicSharedMemorySize, GSMEM_BYTES);
        attr_done = true;
    }

    sinkhorn_kernel<<<NCTA_SINK, 256>>>(ls);
    cvt_kernel<<<4096, 256>>>(reinterpret_cast<const float4*>(emb));
    gemm_kernel<<<(BATCH / 128) * (DIMD / 128), 256, GSMEM_BYTES>>>(out);
}

// round 4
// speedup vs baseline: 1.0819x; 1.0819x over previous
#include <cuda_runtime.h>
#include <cuda_fp16.h>
#include <cstdint>

// ===================== problem constants =====================
#define DIMD 1024
#define BATCH 65536
#define NITERS 20

// fused sinkhorn+cvt config
#define NCTA 256
#define RPC 4              // rows per CTA (256*4 = 1024)
#define NTHR 128
#define N4 (16777216)      // BATCH/4 * DIMD float4 elements of emb
#define CHUNK 3136         // float4 per CTA per barrier: 21*256*3136 >= N4

// ===================== device globals (static scratch; never allocated) =====================
__device__ __half  g_P[DIMD * DIMD];            // Sinkhorn P (row-major = K-major B operand)
__device__ __half  g_A16[(size_t)BATCH * DIMD]; // fp16 embeddings (filled during barrier spins)
__device__ float   g_colSum[NITERS][DIMD];      // per-iter column sums (atomic-accumulated)
__device__ unsigned g_bar;                      // monotonic grid barrier counter
__device__ unsigned g_done;                     // end-of-kernel reset rendezvous

// ===================== small PTX helpers (plain sm_103-legal only) =====================
__device__ __forceinline__ uint32_t smem_to_u32(const void* p) {
    uint32_t a;
    asm("{ .reg .u64 t; cvta.to.shared.u64 t, %1; cvt.u32.u64 %0, t; }" : "=r"(a) : "l"(p));
    return a;
}

#define CP_ASYNC16(dst, src) \
    asm volatile("cp.async.cg.shared.global [%0], [%1], 16;" :: "r"(dst), "l"(src) : "memory")
#define CP_ASYNC_COMMIT() asm volatile("cp.async.commit_group;" ::: "memory")
#define CP_ASYNC_WAIT1()  asm volatile("cp.async.wait_group 1;" ::: "memory")

__device__ __forceinline__ void ldsm_x4(uint32_t* r, uint32_t addr) {
    asm volatile("ldmatrix.sync.aligned.m8n8.x4.shared.b16 {%0,%1,%2,%3}, [%4];"
                 : "=r"(r[0]), "=r"(r[1]), "=r"(r[2]), "=r"(r[3]) : "r"(addr));
}
__device__ __forceinline__ void mma16816(float* d, const uint32_t* a, uint32_t b0, uint32_t b1) {
    asm volatile("mma.sync.aligned.m16n8k16.row.col.f32.f16.f16.f32 "
                 "{%0,%1,%2,%3}, {%4,%5,%6,%7}, {%8,%9}, {%0,%1,%2,%3};"
                 : "+f"(d[0]), "+f"(d[1]), "+f"(d[2]), "+f"(d[3])
                 : "r"(a[0]), "r"(a[1]), "r"(a[2]), "r"(a[3]), "r"(b0), "r"(b1));
}

// ===================== fused Sinkhorn + fp32->fp16 convert =====================
// Grid barrier whose spin window is filled with a deterministic chunk of the
// embeddings fp32->fp16 conversion (384 MB streamed across 21 barriers).
__device__ __forceinline__ void barrier_cvt(int chunk_id, unsigned* tgt,
                                            const float4* __restrict__ emb) {
    __syncthreads();
    if (threadIdx.x == 0) {
        __threadfence();
        atomicAdd(&g_bar, 1u);
    }
    // convert chunk while other CTAs arrive
    {
        const size_t base = ((size_t)chunk_id * NCTA + blockIdx.x) * CHUNK;
        uint2* dst = reinterpret_cast<uint2*>(g_A16);
        #pragma unroll 5
        for (int k = 0; k < CHUNK; k += NTHR) {
            const int l = k + threadIdx.x;
            const size_t idx = base + l;
            if (l < CHUNK && idx < (size_t)N4) {
                const float4 v = emb[idx];
                __half2 h0 = __floats2half2_rn(v.x, v.y);
                __half2 h1 = __floats2half2_rn(v.z, v.w);
                dst[idx] = make_uint2(*reinterpret_cast<const uint32_t*>(&h0),
                                      *reinterpret_cast<const uint32_t*>(&h1));
            }
        }
    }
    if (threadIdx.x == 0) {
        const unsigned t = *tgt;
        while (*((const volatile unsigned*)&g_bar) < t) { }
        __threadfence();
    }
    __syncthreads();
    *tgt += NCTA;
}

__global__ void __launch_bounds__(NTHR)
sinkcvt_kernel(const float* __restrict__ log_scores, const float4* __restrict__ emb) {
    __shared__ float rows[RPC][DIMD];   // 16 KB: e = exp(log_alpha), row-normalized in place
    __shared__ float cs_s[DIMD];        // 4 KB: staged 1/colSum
    const int tid  = threadIdx.x;
    const int warp = tid >> 5;          // 4 warps = 4 rows
    const int lane = tid & 31;
    const int cta  = blockIdx.x;
    const int rbase = cta * RPC;

    // zero this launch's colSum buffers (race covered by barrier 0)
    for (int i = cta * NTHR + tid; i < NITERS * DIMD; i += NCTA * NTHR)
        (&g_colSum[0][0])[i] = 0.f;

    // load rows, go to probability domain (TAU = 1)
    for (int i = tid; i < RPC * DIMD; i += NTHR)
        rows[i >> 10][i & 1023] = __expf(log_scores[(size_t)rbase * DIMD + i]);

    unsigned tgt = NCTA;
    barrier_cvt(0, &tgt, emb);

    for (int iter = 0; iter < NITERS; ++iter) {
        // stage reciprocal column sums from previous iteration
        if (iter > 0) {
            #pragma unroll
            for (int c = tid; c < DIMD; c += NTHR)
                cs_s[c] = __frcp_rn(g_colSum[iter - 1][c]);
            __syncthreads();
        }

        // row normalize: warp w owns row w (fold in pending column division)
        {
            float v[32];
            float s = 0.f;
            #pragma unroll
            for (int j = 0; j < 32; ++j) {
                const int col = lane + j * 32;
                float x = rows[warp][col];
                if (iter > 0) x *= cs_s[col];
                v[j] = x;
                s += x;
            }
            #pragma unroll
            for (int o = 16; o; o >>= 1) s += __shfl_xor_sync(0xFFFFFFFFu, s, o);
            const float inv = __frcp_rn(s);
            #pragma unroll
            for (int j = 0; j < 32; ++j) rows[warp][lane + j * 32] = v[j] * inv;
        }
        __syncthreads();

        // column partial over this CTA's 4 rows -> one atomic per column
        #pragma unroll
        for (int c = 0; c < DIMD / NTHR; ++c) {
            const int col = tid + c * NTHR;
            float p = 0.f;
            #pragma unroll
            for (int r = 0; r < RPC; ++r) p += rows[r][col];
            atomicAdd(&g_colSum[iter][col], p);
        }

        barrier_cvt(iter + 1, &tgt, emb);
    }

    // final: apply last column normalization, emit P as fp16 (K-major B operand)
    #pragma unroll
    for (int c = tid; c < DIMD; c += NTHR)
        cs_s[c] = __frcp_rn(g_colSum[NITERS - 1][c]);
    __syncthreads();
    for (int i = tid; i < RPC * DIMD; i += NTHR) {
        const int r = i >> 10, col = i & 1023;
        g_P[(size_t)(rbase + r) * DIMD + col] = __float2half(rows[r][col] * cs_s[col]);
    }

    // reset barrier counters for the next graph replay
    __syncthreads();
    if (tid == 0) {
        __threadfence();
        atomicAdd(&g_done, 1u);
        if (blockIdx.x == 0) {
            while (*((const volatile unsigned*)&g_done) < NCTA) { }
            g_bar = 0u;
            g_done = 0u;
            __threadfence();
        }
    }
}

// ===================== GEMM: out = A16 @ P^T  (mma.sync m16n8k16, cp.async 3-stage) =====================
// CTA tile 128x128, warp layout 4(m) x 2(n), warp tile 32x64, K-stage 64 (16 stages).
// smem: 3 stages x (A 16KB + B 16KB) = 96KB.  Swizzle: row*128 + (kb ^ ((row&7)<<4)).
#define KSTAGES 16
#define STAGE_BYTES 16384
#define B_BASE (3 * STAGE_BYTES)
#define GSMEM_BYTES (6 * STAGE_BYTES)

__global__ void __launch_bounds__(256, 2)
gemm_kernel(float* __restrict__ out) {
    extern __shared__ __align__(1024) char smem[];
    const uint32_t sb = smem_to_u32(smem);
    const int tid  = threadIdx.x;
    const int wid  = tid >> 5;
    const int lane = tid & 31;

    // ntile fast-moving -> 8 consecutive CTAs share one A row-block (L2 reuse of A)
    const int ntile = blockIdx.x & 7;
    const int mtile = blockIdx.x >> 3;
    const int m0 = mtile * 128;
    const int n0 = ntile * 128;

    const __half* Ag = g_A16 + (size_t)m0 * DIMD;
    const __half* Bg = g_P   + (size_t)n0 * DIMD;

#define ISSUE_STAGE(st, buf)                                                     \
    {                                                                            \
        const __half* asrc = Ag + (st) * 64;                                     \
        const __half* bsrc = Bg + (st) * 64;                                     \
        const uint32_t abase = sb + (buf) * STAGE_BYTES;                         \
        const uint32_t bbase = sb + B_BASE + (buf) * STAGE_BYTES;                \
        _Pragma("unroll")                                                        \
        for (int i = 0; i < 4; ++i) {                                            \
            const int idx = tid + i * 256;                                       \
            const int r = idx >> 3, c = idx & 7;                                 \
            const uint32_t sw = (uint32_t)(r * 128 + ((c * 16) ^ ((r & 7) << 4)));\
            CP_ASYNC16(abase + sw, asrc + (size_t)r * DIMD + c * 8);             \
            CP_ASYNC16(bbase + sw, bsrc + (size_t)r * DIMD + c * 8);             \
        }                                                                        \
        CP_ASYNC_COMMIT();                                                       \
    }

    const int warp_m = wid >> 1;   // 0..3
    const int warp_n = wid & 1;    // 0..1

    int a_pre[2], a_sw[2];
    {
        const int rr = ((lane >> 3) & 1) * 8 + (lane & 7);
        #pragma unroll
        for (int mt = 0; mt < 2; ++mt) {
            const int row = warp_m * 32 + mt * 16 + rr;
            a_pre[mt] = row * 128;
            a_sw[mt]  = (row & 7) << 4;
        }
    }
    const int a_k16 = ((lane >> 4) & 1) * 16;

    int b_pre[4], b_sw[4];
    {
        const int rr = ((lane >> 4) & 1) * 8 + (lane & 7);
        #pragma unroll
        for (int np = 0; np < 4; ++np) {
            const int row = warp_n * 64 + np * 16 + rr;
            b_pre[np] = row * 128;
            b_sw[np]  = (row & 7) << 4;
        }
    }
    const int b_k16 = ((lane >> 3) & 1) * 16;

    float acc[2][8][4];
    #pragma unroll
    for (int mt = 0; mt < 2; ++mt)
        #pragma unroll
        for (int nt = 0; nt < 8; ++nt)
            #pragma unroll
            for (int j = 0; j < 4; ++j) acc[mt][nt][j] = 0.f;

    ISSUE_STAGE(0, 0);
    ISSUE_STAGE(1, 1);

    for (int s = 0; s < KSTAGES; ++s) {
        const int buf = s % 3;
        CP_ASYNC_WAIT1();
        __syncthreads();
        if (s + 2 < KSTAGES) { ISSUE_STAGE(s + 2, (s + 2) % 3); }
        else                 { CP_ASYNC_COMMIT(); }

        const uint32_t Ab = sb + buf * STAGE_BYTES;
        const uint32_t Bb = sb + B_BASE + buf * STAGE_BYTES;
        #pragma unroll
        for (int ks = 0; ks < 4; ++ks) {
            const int kb = ks * 32;
            uint32_t av[2][4];
            #pragma unroll
            for (int mt = 0; mt < 2; ++mt)
                ldsm_x4(av[mt], Ab + a_pre[mt] + ((kb | a_k16) ^ a_sw[mt]));
            uint32_t bv[4][4];
            #pragma unroll
            for (int np = 0; np < 4; ++np)
                ldsm_x4(bv[np], Bb + b_pre[np] + ((kb | b_k16) ^ b_sw[np]));
            #pragma unroll
            for (int mt = 0; mt < 2; ++mt)
                #pragma unroll
                for (int np = 0; np < 4; ++np) {
                    mma16816(acc[mt][2 * np + 0], av[mt], bv[np][0], bv[np][1]);
                    mma16816(acc[mt][2 * np + 1], av[mt], bv[np][2], bv[np][3]);
                }
        }
    }
#undef ISSUE_STAGE

    // epilogue: direct coalesced STG.64
    const int r0c = lane >> 2;
    const int c0c = (lane & 3) * 2;
    #pragma unroll
    for (int mt = 0; mt < 2; ++mt) {
        const int row_base = m0 + warp_m * 32 + mt * 16 + r0c;
        #pragma unroll
        for (int nt = 0; nt < 8; ++nt) {
            const int col = n0 + warp_n * 64 + nt * 8 + c0c;
            float2 v0 = make_float2(acc[mt][nt][0], acc[mt][nt][1]);
            float2 v1 = make_float2(acc[mt][nt][2], acc[mt][nt][3]);
            *reinterpret_cast<float2*>(out + (size_t)row_base * DIMD + col)       = v0;
            *reinterpret_cast<float2*>(out + (size_t)(row_base + 8) * DIMD + col) = v1;
        }
    }
}

// ===================== launch =====================
extern "C" void kernel_launch(void* const* d_in, const int* in_sizes, int n_in,
                              void* d_out, int out_size) {
    const float* emb;
    const float* ls;
    if (n_in >= 2 && in_sizes[0] == DIMD * DIMD && in_sizes[1] != DIMD * DIMD) {
        ls  = (const float*)d_in[0];
        emb = (const float*)d_in[1];
    } else {
        emb = (const float*)d_in[0];
        ls  = (const float*)d_in[1];
    }
    float* out = (float*)d_out;

    static bool attr_done = false;
    if (!attr_done) {
        cudaFuncSetAttribute(gemm_kernel, cudaFuncAttributeMaxDynamicSharedMemorySize, GSMEM_BYTES);
        attr_done = true;
    }

    sinkcvt_kernel<<<NCTA, NTHR>>>(ls, reinterpret_cast<const float4*>(emb));
    gemm_kernel<<<(BATCH / 128) * (DIMD / 128), 256, GSMEM_BYTES>>>(out);
}